// round 1
// baseline (speedup 1.0000x reference)
#include <cuda_runtime.h>

#define B_TOT 16384
#define F 39
#define E 16
#define D 16
#define H 2
#define DH 8
#define NT 128
#define ATT_STRIDE 40   // padded row stride for att matrix (alignment + conflict relief)

__global__ __launch_bounds__(NT)
void self_attn_interaction_kernel(
    const float* __restrict__ x,
    const float* __restrict__ Wq,
    const float* __restrict__ Wk,
    const float* __restrict__ Wv,
    const float* __restrict__ Wr,
    float* __restrict__ out)
{
    __shared__ float sW[4][E * D];              // 4 KB: Q,K,V,Res weights
    __shared__ float sx[F * E];                 // x tile      (39x16)
    __shared__ float sq[F * D];                 // Q           (39x16)
    __shared__ float sk[F * D];                 // K
    __shared__ float sv[F * D];                 // V
    __shared__ float sr[F * D];                 // x @ W_Res
    __shared__ float satt[H * F * ATT_STRIDE];  // exp(scores), rows padded to 40
    __shared__ float ssum[H * F];               // softmax row sums

    const int t = threadIdx.x;
    const int b = blockIdx.x;
    const float* xb = x + (size_t)b * (F * E);

    // ---- stage weights + x ----
    for (int i = t; i < E * D; i += NT) {
        sW[0][i] = Wq[i];
        sW[1][i] = Wk[i];
        sW[2][i] = Wv[i];
        sW[3][i] = Wr[i];
    }
    {
        const float4* x4 = (const float4*)xb;
        float4* sx4 = (float4*)sx;
        for (int i = t; i < (F * E) / 4; i += NT) sx4[i] = x4[i];
    }
    __syncthreads();

    // ---- phase 1: projections  q,k,v,res = x @ W_* ----
    // thread owns output column j; weight columns live in registers,
    // x rows come from SMEM as float4 (2-way broadcast within a warp).
    {
        const int j  = t & 15;
        const int g0 = t >> 4;          // 8 f-groups
        float wq[16], wk[16], wv[16], wr[16];
        #pragma unroll
        for (int i = 0; i < 16; i++) {
            wq[i] = sW[0][i * 16 + j];
            wk[i] = sW[1][i * 16 + j];
            wv[i] = sW[2][i * 16 + j];
            wr[i] = sW[3][i * 16 + j];
        }
        for (int f = g0; f < F; f += 8) {
            const float4* xr4 = (const float4*)(sx + f * 16);
            float xr[16];
            #pragma unroll
            for (int i4 = 0; i4 < 4; i4++) {
                float4 v4 = xr4[i4];
                xr[4 * i4 + 0] = v4.x; xr[4 * i4 + 1] = v4.y;
                xr[4 * i4 + 2] = v4.z; xr[4 * i4 + 3] = v4.w;
            }
            float aq = 0.f, ak = 0.f, av = 0.f, ar = 0.f;
            #pragma unroll
            for (int i = 0; i < 16; i++) {
                aq = fmaf(xr[i], wq[i], aq);
                ak = fmaf(xr[i], wk[i], ak);
                av = fmaf(xr[i], wv[i], av);
                ar = fmaf(xr[i], wr[i], ar);
            }
            sq[f * 16 + j] = aq;
            sk[f * 16 + j] = ak;
            sv[f * 16 + j] = av;
            sr[f * 16 + j] = ar;
        }
    }
    __syncthreads();

    // ---- phase 2: scores -> exp -> row sum (one (h,f) row per thread) ----
    // softmax normalization deferred: store un-normalized exp + row sum.
    if (t < H * F) {
        const int h  = t / F;
        const int fq = t - h * F;
        float qv[DH];
        #pragma unroll
        for (int dd = 0; dd < DH; dd++) qv[dd] = sq[fq * 16 + h * 8 + dd];
        float* arow = satt + t * ATT_STRIDE;
        float sum = 0.f;
        for (int g = 0; g < F; g++) {
            const float* kr = sk + g * 16 + h * 8;
            float s = 0.f;
            #pragma unroll
            for (int dd = 0; dd < DH; dd++) s = fmaf(qv[dd], kr[dd], s);
            float e = __expf(s);
            arow[g] = e;
            sum += e;
        }
        ssum[t] = sum;
    }
    __syncthreads();

    // ---- phase 3: out = att @ V / rowsum + res, ReLU, store ----
    // thread owns output column c; V column register-resident across its 5 rows.
    {
        const int c  = t & 15;
        const int h  = c >> 3;
        const int g0 = t >> 4;
        float vcol[F];
        #pragma unroll
        for (int g = 0; g < F; g++) vcol[g] = sv[g * 16 + c];
        float* ob = out + (size_t)b * (F * E);
        for (int f = g0; f < F; f += 8) {
            const float* arow = satt + (h * F + f) * ATT_STRIDE;
            float acc = 0.f;
            #pragma unroll
            for (int g = 0; g < F; g++) acc = fmaf(arow[g], vcol[g], acc);
            float o = acc / ssum[h * F + f] + sr[f * 16 + c];
            ob[f * 16 + c] = fmaxf(o, 0.f);
        }
    }
}

extern "C" void kernel_launch(void* const* d_in, const int* in_sizes, int n_in,
                              void* d_out, int out_size)
{
    const float* x  = (const float*)d_in[0];
    const float* Wq = (const float*)d_in[1];
    const float* Wk = (const float*)d_in[2];
    const float* Wv = (const float*)d_in[3];
    const float* Wr = (const float*)d_in[4];
    float* out = (float*)d_out;
    self_attn_interaction_kernel<<<B_TOT, NT>>>(x, Wq, Wk, Wv, Wr, out);
}

// round 2
// speedup vs baseline: 1.7144x; 1.7144x over previous
#include <cuda_runtime.h>

#define B_TOT 16384
#define F 39
#define E 16
#define D 16
#define H 2
#define DH 8
#define NT 128
#define ATT_STRIDE 44     // 16B-aligned; (11t+k)%8 permutes -> conflict-free STS.128/LDS.128

// sW padded to 264 floats per matrix: pair-accessed matrices (0,2) and (1,3)
// have base-offset diff 528 ≡ 16 (mod 32 banks) -> conflict-free divergent loads.
#define WPAD 264

// sproj offsets: Q=0, K=640, V=1296, R=1936  (V-Q ≡ 16, R-K ≡ 16 mod 32 banks,
// all 16B-aligned) -> conflict-free pair stores and float4 reads.
#define OFF_Q 0
#define OFF_K 640
#define OFF_V 1296
#define OFF_R 1936
#define SPROJ_SZ 2560

__global__ __launch_bounds__(NT)
void self_attn_interaction_kernel(
    const float* __restrict__ x,
    const float* __restrict__ Wq,
    const float* __restrict__ Wk,
    const float* __restrict__ Wv,
    const float* __restrict__ Wr,
    float* __restrict__ out)
{
    __shared__ float sW[4][WPAD];
    __shared__ float sx[F * E];
    __shared__ float sproj[SPROJ_SZ];               // Q,K,V,Res projections
    __shared__ float satt[H * F * ATT_STRIDE];      // exp(scores), rows padded to 40 (+4 slack)
    __shared__ float ssum[H * F];

    const int t = threadIdx.x;
    const int b = blockIdx.x;
    const float* xb = x + (size_t)b * (F * E);

    // ---- stage weights + x ----
    for (int i = t; i < E * D; i += NT) {
        sW[0][i] = Wq[i];
        sW[1][i] = Wk[i];
        sW[2][i] = Wv[i];
        sW[3][i] = Wr[i];
    }
    {
        const float4* x4 = (const float4*)xb;
        float4* sx4 = (float4*)sx;
        for (int i = t; i < (F * E) / 4; i += NT) sx4[i] = x4[i];
    }
    __syncthreads();

    // ---- phase 1: projections ----
    // thread = (j, pair p, f-quarter). p=0 -> {Q,K}, p=1 -> {V,Res}.
    // 32 weight regs/thread; x row broadcast to the whole warp.
    {
        const int j  = t & 15;
        const int s  = t >> 4;          // 0..7
        const int p  = s & 1;           // matrix pair
        const int f0 = s >> 1;          // 0..3
        const float* WA = sW[p * 2];
        const float* WB = sW[p * 2 + 1];
        float* outA = sproj + (p ? OFF_V : OFF_Q);
        float* outB = sproj + (p ? OFF_R : OFF_K);

        float wa[16], wb[16];
        #pragma unroll
        for (int i = 0; i < 16; i++) {
            wa[i] = WA[i * 16 + j];
            wb[i] = WB[i * 16 + j];
        }
        for (int f = f0; f < F; f += 4) {
            const float4* xr4 = (const float4*)(sx + f * 16);
            float xr[16];
            #pragma unroll
            for (int i4 = 0; i4 < 4; i4++) {
                float4 v4 = xr4[i4];
                xr[4 * i4 + 0] = v4.x; xr[4 * i4 + 1] = v4.y;
                xr[4 * i4 + 2] = v4.z; xr[4 * i4 + 3] = v4.w;
            }
            float aa = 0.f, ab = 0.f;
            #pragma unroll
            for (int i = 0; i < 16; i++) {
                aa = fmaf(xr[i], wa[i], aa);
                ab = fmaf(xr[i], wb[i], ab);
            }
            outA[f * 16 + j] = aa;
            outB[f * 16 + j] = ab;
        }
    }
    __syncthreads();

    // ---- phase 2: scores -> exp -> row sum (one (h,f) row per thread) ----
    if (t < H * F) {
        const int h  = t / F;
        const int fq = t - h * F;
        const float4* q4 = (const float4*)(sproj + OFF_Q + fq * 16 + h * 8);
        float4 qa = q4[0], qb = q4[1];

        float* arow = satt + t * ATT_STRIDE;
        float sum = 0.f;
        #pragma unroll 2
        for (int gb = 0; gb < 10; gb++) {
            float4 e4;
            float ev[4];
            #pragma unroll
            for (int u = 0; u < 4; u++) {
                const int g = gb * 4 + u;
                float e = 0.f;
                if (g < F) {
                    const float4* k4 = (const float4*)(sproj + OFF_K + g * 16 + h * 8);
                    float4 ka = k4[0], kb = k4[1];
                    float sc = qa.x * ka.x + qa.y * ka.y + qa.z * ka.z + qa.w * ka.w
                             + qb.x * kb.x + qb.y * kb.y + qb.z * kb.z + qb.w * kb.w;
                    e = __expf(sc);
                    sum += e;
                }
                ev[u] = e;
            }
            e4.x = ev[0]; e4.y = ev[1]; e4.z = ev[2]; e4.w = ev[3];
            ((float4*)arow)[gb] = e4;
        }
        ssum[t] = sum;
    }
    __syncthreads();

    // ---- phase 3: out = att @ V / rowsum + res, ReLU, store ----
    {
        const int c  = t & 15;
        const int h  = c >> 3;
        const int g0 = t >> 4;
        float vcol[40];
        #pragma unroll
        for (int g = 0; g < F; g++) vcol[g] = sproj[OFF_V + g * 16 + c];
        vcol[39] = 0.f;

        float* ob = out + (size_t)b * (F * E);
        for (int f = g0; f < F; f += 8) {
            const float4* a4 = (const float4*)(satt + (h * F + f) * ATT_STRIDE);
            float acc = 0.f;
            #pragma unroll
            for (int gb = 0; gb < 10; gb++) {
                float4 av = a4[gb];
                acc = fmaf(av.x, vcol[4 * gb + 0], acc);
                acc = fmaf(av.y, vcol[4 * gb + 1], acc);
                acc = fmaf(av.z, vcol[4 * gb + 2], acc);
                acc = fmaf(av.w, vcol[4 * gb + 3], acc);
            }
            float o = acc / ssum[h * F + f] + sproj[OFF_R + f * 16 + c];
            ob[f * 16 + c] = fmaxf(o, 0.f);
        }
    }
}

extern "C" void kernel_launch(void* const* d_in, const int* in_sizes, int n_in,
                              void* d_out, int out_size)
{
    const float* x  = (const float*)d_in[0];
    const float* Wq = (const float*)d_in[1];
    const float* Wk = (const float*)d_in[2];
    const float* Wv = (const float*)d_in[3];
    const float* Wr = (const float*)d_in[4];
    float* out = (float*)d_out;
    self_attn_interaction_kernel<<<B_TOT, NT>>>(x, Wq, Wk, Wv, Wr, out);
}

// round 3
// speedup vs baseline: 1.9208x; 1.1204x over previous
#include <cuda_runtime.h>
#include <cstdint>

#define B_TOT 16384
#define F 39
#define E 16
#define D 16
#define NT 128
#define PS 20   // padded row stride (floats): 20j mod 32 is a bank permutation, 16B-aligned rows

// transposed-weight offsets in sWT (stride PS, [j][i] layout, 16 rows each = 320 floats)
#define WT_Q 0
#define WT_K 320
#define WT_V 656    // 656 % 32 == 16  -> disjoint banks vs WT_Q on paired loads
#define WT_R 976    // (976-320) % 32 == 16 -> disjoint vs WT_K
#define WT_SZ 1296

// projection offsets in sproj (stride PS, 39 rows each = 780 floats)
#define OFF_Q 0
#define OFF_K 784
#define OFF_V 1584  // (1584-0)   % 32 == 16
#define OFF_R 2368  // (2368-784) % 32 == 16
#define SPROJ_SZ 3148

__device__ __forceinline__ void fma2(uint64_t& d, uint64_t a, uint64_t b) {
    asm("fma.rn.f32x2 %0, %1, %2, %0;" : "+l"(d) : "l"(a), "l"(b));
}
__device__ __forceinline__ uint64_t add2(uint64_t a, uint64_t b) {
    uint64_t r; asm("add.rn.f32x2 %0, %1, %2;" : "=l"(r) : "l"(a), "l"(b)); return r;
}
__device__ __forceinline__ uint64_t pk2(float lo, float hi) {
    uint64_t r; asm("mov.b64 %0, {%1, %2};" : "=l"(r) : "f"(lo), "f"(hi)); return r;
}
__device__ __forceinline__ float hadd2(uint64_t p) {
    float lo, hi; asm("mov.b64 {%0, %1}, %2;" : "=f"(lo), "=f"(hi) : "l"(p)); return lo + hi;
}
__device__ __forceinline__ void unpk2(uint64_t p, float& lo, float& hi) {
    asm("mov.b64 {%0, %1}, %2;" : "=f"(lo), "=f"(hi) : "l"(p));
}

__global__ __launch_bounds__(NT)
void self_attn_interaction_kernel(
    const float* __restrict__ x,
    const float* __restrict__ Wq,
    const float* __restrict__ Wk,
    const float* __restrict__ Wv,
    const float* __restrict__ Wr,
    float* __restrict__ out)
{
    __shared__ __align__(16) float sWT[WT_SZ];      // transposed weights [j][i], stride PS
    __shared__ __align__(16) float sx[F * E];       // x tile (rows contiguous, 16 floats)
    __shared__ __align__(16) float sproj[SPROJ_SZ]; // Q,K,V,Res rows, stride PS

    const int t = threadIdx.x;
    const int b = blockIdx.x;
    const float* xb = x + (size_t)b * (F * E);

    // ---- stage: weights (transposed into [j][i]) + x ----
    for (int e = t; e < E * D; e += NT) {
        const int i = e >> 4, j = e & 15;
        const int o = j * PS + i;
        sWT[WT_Q + o] = Wq[e];
        sWT[WT_K + o] = Wk[e];
        sWT[WT_V + o] = Wv[e];
        sWT[WT_R + o] = Wr[e];
    }
    {
        const float4* x4 = (const float4*)xb;
        float4* sx4 = (float4*)sx;
        for (int i = t; i < (F * E) / 4; i += NT) sx4[i] = x4[i];
    }
    __syncthreads();

    // ---- phase 1: projections (packed f32x2, weights register-resident) ----
    {
        const int j  = t & 15;
        const int s  = t >> 4;
        const int p  = s & 1;          // 0 -> {Q,K}, 1 -> {V,Res}
        const int f0 = s >> 1;         // 0..3
        const ulonglong2* wta = (const ulonglong2*)(sWT + (p ? WT_V : WT_Q) + j * PS);
        const ulonglong2* wtb = (const ulonglong2*)(sWT + (p ? WT_R : WT_K) + j * PS);
        float* outA = sproj + (p ? OFF_V : OFF_Q);
        float* outB = sproj + (p ? OFF_R : OFF_K);

        uint64_t wa[8], wb[8];
        #pragma unroll
        for (int u = 0; u < 4; u++) {
            ulonglong2 a = wta[u], c = wtb[u];
            wa[2 * u] = a.x; wa[2 * u + 1] = a.y;
            wb[2 * u] = c.x; wb[2 * u + 1] = c.y;
        }
        for (int f = f0; f < F; f += 4) {
            const ulonglong2* xr2 = (const ulonglong2*)(sx + f * 16);
            uint64_t xp[8];
            #pragma unroll
            for (int u = 0; u < 4; u++) {
                ulonglong2 v = xr2[u];
                xp[2 * u] = v.x; xp[2 * u + 1] = v.y;
            }
            uint64_t accA = 0ull, accB = 0ull;
            #pragma unroll
            for (int i = 0; i < 8; i++) {
                fma2(accA, xp[i], wa[i]);
                fma2(accB, xp[i], wb[i]);
            }
            outA[f * PS + j] = hadd2(accA);
            outB[f * PS + j] = hadd2(accB);
        }
    }
    __syncthreads();

    // ---- fused phase 2+3: streaming softmax-attention (one (h,f) row per thread) ----
    if (t < 2 * F) {
        const int h  = (t < F) ? 0 : 1;
        const int fq = t - h * F;

        const ulonglong2* q2 = (const ulonglong2*)(sproj + OFF_Q + fq * PS + h * 8);
        ulonglong2 qa = q2[0], qb = q2[1];
        uint64_t qp0 = qa.x, qp1 = qa.y, qp2 = qb.x, qp3 = qb.y;

        uint64_t acc0 = 0ull, acc1 = 0ull, acc2 = 0ull, acc3 = 0ull;
        float sum = 0.f;
        const float* kbase = sproj + OFF_K + h * 8;
        const float* vbase = sproj + OFF_V + h * 8;

        #pragma unroll 3
        for (int g = 0; g < F; g++) {
            const ulonglong2* k2 = (const ulonglong2*)(kbase + g * PS);
            const ulonglong2* v2 = (const ulonglong2*)(vbase + g * PS);
            ulonglong2 ku = k2[0], kv = k2[1];
            uint64_t sp0 = 0ull, sp1 = 0ull;
            fma2(sp0, qp0, ku.x); fma2(sp1, qp1, ku.y);
            fma2(sp0, qp2, kv.x); fma2(sp1, qp3, kv.y);
            float sc = hadd2(add2(sp0, sp1));
            float e = __expf(sc);
            sum += e;
            uint64_t ee = pk2(e, e);
            ulonglong2 vu = v2[0], vv = v2[1];
            fma2(acc0, ee, vu.x); fma2(acc1, ee, vu.y);
            fma2(acc2, ee, vv.x); fma2(acc3, ee, vv.y);
        }

        const float rinv = __fdividef(1.f, sum);
        const uint64_t rp = pk2(rinv, rinv);
        const ulonglong2* r2 = (const ulonglong2*)(sproj + OFF_R + fq * PS + h * 8);
        ulonglong2 ru = r2[0], rv = r2[1];

        uint64_t o0 = ru.x, o1 = ru.y, o2 = rv.x, o3 = rv.y;
        fma2(o0, acc0, rp); fma2(o1, acc1, rp);
        fma2(o2, acc2, rp); fma2(o3, acc3, rp);

        float4 w0, w1;
        unpk2(o0, w0.x, w0.y); unpk2(o1, w0.z, w0.w);
        unpk2(o2, w1.x, w1.y); unpk2(o3, w1.z, w1.w);
        w0.x = fmaxf(w0.x, 0.f); w0.y = fmaxf(w0.y, 0.f);
        w0.z = fmaxf(w0.z, 0.f); w0.w = fmaxf(w0.w, 0.f);
        w1.x = fmaxf(w1.x, 0.f); w1.y = fmaxf(w1.y, 0.f);
        w1.z = fmaxf(w1.z, 0.f); w1.w = fmaxf(w1.w, 0.f);

        float* ob = out + (size_t)b * (F * E) + fq * 16 + h * 8;
        ((float4*)ob)[0] = w0;
        ((float4*)ob)[1] = w1;
    }
}

extern "C" void kernel_launch(void* const* d_in, const int* in_sizes, int n_in,
                              void* d_out, int out_size)
{
    const float* x  = (const float*)d_in[0];
    const float* Wq = (const float*)d_in[1];
    const float* Wk = (const float*)d_in[2];
    const float* Wv = (const float*)d_in[3];
    const float* Wr = (const float*)d_in[4];
    float* out = (float*)d_out;
    self_attn_interaction_kernel<<<B_TOT, NT>>>(x, Wq, Wk, Wv, Wr, out);
}